// round 15
// baseline (speedup 1.0000x reference)
#include <cuda_runtime.h>
#include <cuda_fp16.h>
#include <math.h>
#include <stdint.h>

#define NA 20000
#define NAP 20096           // padded rows (157*128)
#define MT (NAP / 128)      // 157 m-tiles
#define NP 800000
#define NSP 119
#define NB 7
#define RMAXV 6.0f
#define PI_F 3.14159265358979323846f
#define CAP 64              // per-atom neighbor capacity (lambda~15, P(>=64)~1e-20)

#define KP1 384             // 360 padded to 64-element k-tiles (plain fp16)
#define KP2 512
#define U 512
#define IN_SCALE 0.00390625f   // 2^-8 applied to GEMM A inputs

#define P1_BLOCKS 3125
#define W1_ELEMS (360 * 512)
#define W2_ELEMS (512 * 512)
#define W_BLOCKS ((W1_ELEMS + W2_ELEMS + 255) / 256)   // 1744

// ---------------------------------------------------------------------------
// device scratch (static; zero at module load; pads never written)
// ---------------------------------------------------------------------------
__device__ int    g_cur[NA];
__device__ int    g_tilecnt[MT];
__device__ float  g_outacc[NA];
__device__ float4 g_Rz[NA];                       // packed R.xyz + Z bits
__device__ float  g_embp[NSP * NSP * 36];         // emb rows padded 35->36
__device__ float  g_prod[(size_t)NA * CAP * 8];   // per active pair: rad[5]+dn[3]
__device__ __half g_A1[(size_t)NAP * KP1];        // feats (scaled), plain fp16
__device__ __half g_B1[(size_t)U * KP1];          // W1^T fp16
__device__ __half g_A2[(size_t)NAP * KP2];        // h1 (scaled), plain fp16
__device__ __half g_B2[(size_t)U * KP2];          // W2^T fp16

// ---------------------------------------------------------------------------
// helpers
// ---------------------------------------------------------------------------
__device__ __forceinline__ uint32_t smem_u32(const void* p) {
    uint32_t a;
    asm("{ .reg .u64 t; cvta.to.shared.u64 t, %1; cvt.u32.u64 %0, t; }" : "=r"(a) : "l"(p));
    return a;
}
#define CP16(dst, src)   asm volatile("cp.async.cg.shared.global [%0], [%1], 16;" :: "r"(dst), "l"(src))
#define CP_COMMIT()      asm volatile("cp.async.commit_group;" ::: "memory")
#define CP_WAIT(n)       asm volatile("cp.async.wait_group %0;" :: "n"(n) : "memory")
#define GDC_WAIT()       asm volatile("griddepcontrol.wait;" ::: "memory")

__device__ __forceinline__ void ldm_x4(uint32_t& r0, uint32_t& r1, uint32_t& r2, uint32_t& r3,
                                       uint32_t addr) {
    asm volatile("ldmatrix.sync.aligned.m8n8.x4.shared.b16 {%0,%1,%2,%3}, [%4];"
                 : "=r"(r0), "=r"(r1), "=r"(r2), "=r"(r3) : "r"(addr));
}
__device__ __forceinline__ void mma16816(float* d, const uint32_t* a, const uint32_t* b) {
    asm volatile("mma.sync.aligned.m16n8k16.row.col.f32.f16.f16.f32 "
                 "{%0,%1,%2,%3}, {%4,%5,%6,%7}, {%8,%9}, {%0,%1,%2,%3};"
                 : "+f"(d[0]), "+f"(d[1]), "+f"(d[2]), "+f"(d[3])
                 : "r"(a[0]), "r"(a[1]), "r"(a[2]), "r"(a[3]), "r"(b[0]), "r"(b[1]));
}
__device__ __forceinline__ void redf(float* p, float v) {
    asm volatile("red.global.add.f32 [%0], %1;" :: "l"(p), "f"(v) : "memory");
}
__device__ __forceinline__ uint32_t h16(float v) {
    return (uint32_t)__half_as_ushort(__float2half(v));
}

// symmetric index maps (compile-time folded)
__device__ __forceinline__ int imap2(int a, int b) {
    int i = a < b ? a : b, j = a < b ? b : a;
    return (i == 0) ? j : ((i == 1) ? (2 + j) : 5);
}
__device__ __forceinline__ int imap3(int a, int b, int c) {
    int i = a, j = b, k = c, t;
    if (i > j) { t = i; i = j; j = t; }
    if (j > k) { t = j; j = k; k = t; }
    if (i > j) { t = i; i = j; j = t; }
    if (i == 0) return imap2(j, k);
    if (i == 1) return (j == 1) ? (5 + k) : 8;
    return 9;
}

// ---------------------------------------------------------------------------
// prep: zero counters/outacc/tilecnt, pack R+Z, pad emb rows (one kernel)
// ---------------------------------------------------------------------------
#define EMBP_N (NSP * NSP * 36)
__global__ void prep_kernel(const float* __restrict__ R, const int* __restrict__ Z,
                            const float* __restrict__ emb) {
    int i = blockIdx.x * blockDim.x + threadIdx.x;
    if (i < EMBP_N) {
        int pair = i / 36, c = i - pair * 36;
        g_embp[i] = (c < 35) ? emb[(size_t)pair * 35 + c] : 0.f;
    }
    if (i < NA) {
        g_cur[i] = 0;
        g_outacc[i] = 0.f;
        g_Rz[i] = make_float4(R[3 * i], R[3 * i + 1], R[3 * i + 2], __int_as_float(Z[i]));
    }
    if (i < MT) g_tilecnt[i] = 0;
}

// ---------------------------------------------------------------------------
// p1 + wprep fused by block range. Direct 7-expf basis.
// ---------------------------------------------------------------------------
__global__ void p1w_kernel(const int* __restrict__ nbr, const float* __restrict__ off,
                           const float* __restrict__ W1, const float* __restrict__ W2) {
    if (blockIdx.x >= P1_BLOCKS) {
        // weight conversion: independent of prep outputs -> no griddep wait
        int idx = (blockIdx.x - P1_BLOCKS) * 256 + threadIdx.x;
        if (idx < W1_ELEMS) {
            int n = idx / 360, k = idx - n * 360;
            float w = __ldg(W1 + (size_t)k * 512 + n);
            *(__half*)((char*)g_B1 + (size_t)n * (KP1 * 2) + 2 * k) = __float2half(w);
        } else {
            idx -= W1_ELEMS;
            if (idx < W2_ELEMS) {
                int n = idx >> 9, k = idx & 511;
                float w = __ldg(W2 + (size_t)k * 512 + n);
                *(__half*)((char*)g_B2 + (size_t)n * (KP2 * 2) + 2 * k) = __float2half(w);
            }
        }
        return;
    }

    GDC_WAIT();   // needs g_Rz / g_embp / g_cur from prep

    int p = blockIdx.x * blockDim.x + threadIdx.x;
    if (p >= NP) return;
    int ia = nbr[p], ja = nbr[NP + p];

    float4 ri = __ldg(&g_Rz[ia]);
    float4 rj = __ldg(&g_Rz[ja]);
    float dx = rj.x - ri.x + off[p * 3 + 0];
    float dy = rj.y - ri.y + off[p * 3 + 1];
    float dz = rj.z - ri.z + off[p * 3 + 2];
    float dr = sqrtf(dx * dx + dy * dy + dz * dz);
    if (!(dr < RMAXV)) return;

    float inv = 1.0f / (dr + 1e-5f);
    float dn0 = dx * inv, dn1 = dy * inv, dn2 = dz * inv;

    const float betta = 49.0f / 36.0f;
    const float rad_norm = 0.898112f;   // (2*betta/pi)^0.75
    float cut = 0.5f * (cosf(PI_F * dr * (1.0f / RMAXV)) + 1.0f);

    float basis[NB];
#pragma unroll
    for (int b = 0; b < NB; b++) {
        float t = dr - (0.5f + 0.91666666666666667f * (float)b);
        basis[b] = rad_norm * expf(-betta * t * t);
    }

    int zi = __float_as_int(ri.w), zj = __float_as_int(rj.w);
    const float4* e4 = (const float4*)(g_embp + (size_t)(zj * NSP + zi) * 36);
    float ev[36];
#pragma unroll
    for (int q = 0; q < 9; q++) {
        float4 t = __ldg(e4 + q);
        ev[4 * q] = t.x; ev[4 * q + 1] = t.y; ev[4 * q + 2] = t.z; ev[4 * q + 3] = t.w;
    }

    float pref = 0.37796447300922720f * cut;
    float rad[5];
#pragma unroll
    for (int r = 0; r < 5; r++) {
        float s = 0.f;
#pragma unroll
        for (int b = 0; b < NB; b++) s += ev[r * NB + b] * basis[b];
        rad[r] = pref * s;
    }

    int slot = atomicAdd(&g_cur[ia], 1);
    if (slot >= CAP) return;   // statistically impossible (P ~ 1e-20)
    float* pb = g_prod + ((size_t)ia * CAP + slot) * 8;
    ((float4*)pb)[0] = make_float4(rad[0], rad[1], rad[2], rad[3]);
    ((float4*)pb)[1] = make_float4(rad[4], dn0, dn1, dn2);
}

// ---------------------------------------------------------------------------
// fused p2+feat: 192 threads / 32 atoms per block
// ---------------------------------------------------------------------------
#define M2F(r, x, y) m2[r][imap2((x), (y))]
#define M3F(r, x, y, z) m3[r][imap3((x), (y), (z))]
#define MLD 101
#define SFLD 361
#define PFSMEM ((32 * MLD + 32 * SFLD) * 4)

__global__ void __launch_bounds__(192) p2feat_kernel() {
    extern __shared__ float sm[];
    float* smM = sm;                 // [32][MLD]
    float* sf = sm + 32 * MLD;       // [32][SFLD]
    const int tid = threadIdx.x;

    GDC_WAIT();   // needs g_cur / g_prod from p1w

    if (tid < 160) {
        int aL = tid / 5, r = tid - aL * 5;
        int a = blockIdx.x * 32 + aL;
        if (a < NA) {
            int n = g_cur[a];
            if (n > CAP) n = CAP;
            const float* base = g_prod + (size_t)a * CAP * 8;
            float acc[20];
#pragma unroll
            for (int j = 0; j < 20; j++) acc[j] = 0.f;
            for (int s = 0; s < n; s++) {
                float rv = __ldg(base + s * 8 + r);
                float4 v = __ldg((const float4*)(base + s * 8 + 4));
                float dn0 = v.y, dn1 = v.z, dn2 = v.w;
                float q00 = dn0 * dn0, q01 = dn0 * dn1, q02 = dn0 * dn2;
                float q11 = dn1 * dn1, q12 = dn1 * dn2, q22 = dn2 * dn2;
                acc[0] += rv;
                acc[1] += rv * dn0;  acc[2] += rv * dn1;  acc[3] += rv * dn2;
                acc[4] += rv * q00;  acc[5] += rv * q01;  acc[6] += rv * q02;
                acc[7] += rv * q11;  acc[8] += rv * q12;  acc[9] += rv * q22;
                acc[10] += rv * q00 * dn0;  acc[11] += rv * q00 * dn1;  acc[12] += rv * q00 * dn2;
                acc[13] += rv * q11 * dn0;  acc[14] += rv * q01 * dn2;  acc[15] += rv * q22 * dn0;
                acc[16] += rv * q11 * dn1;  acc[17] += rv * q11 * dn2;  acc[18] += rv * q22 * dn1;
                acc[19] += rv * q22 * dn2;
            }
            float* dst = smM + aL * MLD + r * 20;
#pragma unroll
            for (int j = 0; j < 20; j++) dst[j] = acc[j];
        }
    }
    __syncthreads();

    const int role = tid >> 5;
    const int aL = tid & 31;
    const int a = blockIdx.x * 32 + aL;
    if (role < 4 && a < NA) {
        const float* v = smM + aL * MLD;
        float* F = sf + aL * SFLD;
        if (role == 0) {
            int pos = 0;
            float m0[5];
#pragma unroll
            for (int r = 0; r < 5; r++) m0[r] = v[r * 20];
#pragma unroll
            for (int r = 0; r < 5; r++) F[pos++] = m0[r];
            float m1[5][3];
#pragma unroll
            for (int r = 0; r < 5; r++)
#pragma unroll
                for (int i = 0; i < 3; i++) m1[r][i] = v[r * 20 + 1 + i];
#pragma unroll
            for (int r = 0; r < 5; r++)
#pragma unroll
                for (int s = 0; s <= r; s++) {
                    float acc = 0.f;
#pragma unroll
                    for (int i = 0; i < 3; i++) acc += m1[r][i] * m1[s][i];
                    F[pos++] = acc;
                }
            float m2[5][6];
#pragma unroll
            for (int r = 0; r < 5; r++)
#pragma unroll
                for (int q = 0; q < 6; q++) m2[r][q] = v[r * 20 + 4 + q];
            const float w2[6] = {1.f, 2.f, 2.f, 1.f, 2.f, 1.f};
#pragma unroll
            for (int r = 0; r < 5; r++)
#pragma unroll
                for (int s = 0; s <= r; s++) {
                    float acc = 0.f;
#pragma unroll
                    for (int q = 0; q < 6; q++) acc += w2[q] * m2[r][q] * m2[s][q];
                    F[pos++] = acc;
                }
            {
                float m3[5][10];
#pragma unroll
                for (int r = 0; r < 5; r++)
#pragma unroll
                    for (int q = 0; q < 10; q++) m3[r][q] = v[r * 20 + 10 + q];
                const float w3[10] = {1.f, 3.f, 3.f, 3.f, 6.f, 3.f, 1.f, 3.f, 3.f, 1.f};
#pragma unroll
                for (int r = 0; r < 5; r++)
#pragma unroll
                    for (int s = 0; s <= r; s++) {
                        float acc = 0.f;
#pragma unroll
                        for (int q = 0; q < 10; q++) acc += w3[q] * m3[r][q] * m3[s][q];
                        F[pos++] = acc;
                    }
            }
#pragma unroll
            for (int r = 0; r < 5; r++)
#pragma unroll
                for (int s = 0; s <= r; s++)
#pragma unroll
                    for (int t = 0; t <= s; t++) {
                        float acc = 0.f;
#pragma unroll
                        for (int x = 0; x < 3; x++)
#pragma unroll
                            for (int y = 0; y < 3; y++)
#pragma unroll
                                for (int z = 0; z < 3; z++)
                                    acc += M2F(r, x, y) * M2F(s, x, z) * M2F(t, y, z);
                        F[pos++] = acc;
                    }
        } else if (role == 1) {
            int pos = 85;
            float m1[5][3], m2[5][6];
#pragma unroll
            for (int r = 0; r < 5; r++) {
#pragma unroll
                for (int i = 0; i < 3; i++) m1[r][i] = v[r * 20 + 1 + i];
#pragma unroll
                for (int q = 0; q < 6; q++) m2[r][q] = v[r * 20 + 4 + q];
            }
#pragma unroll
            for (int r = 0; r < 5; r++)
#pragma unroll
                for (int s = 0; s <= r; s++)
#pragma unroll
                    for (int t = 0; t < 5; t++) {
                        float acc = 0.f;
#pragma unroll
                        for (int x = 0; x < 3; x++)
#pragma unroll
                            for (int y = 0; y < 3; y++)
                                acc += m1[r][x] * m1[s][y] * M2F(t, x, y);
                        F[pos++] = acc;
                    }
        } else if (role == 2) {
            int pos = 160;
            float m2[5][6], m3[5][10];
#pragma unroll
            for (int r = 0; r < 5; r++) {
#pragma unroll
                for (int q = 0; q < 6; q++) m2[r][q] = v[r * 20 + 4 + q];
#pragma unroll
                for (int q = 0; q < 10; q++) m3[r][q] = v[r * 20 + 10 + q];
            }
#pragma unroll
            for (int r = 0; r < 5; r++)
#pragma unroll
                for (int s = 0; s <= r; s++) {
                    float A[3][3];
#pragma unroll
                    for (int k = 0; k < 3; k++)
#pragma unroll
                        for (int l = 0; l < 3; l++) {
                            float acc = 0.f;
#pragma unroll
                            for (int x = 0; x < 3; x++)
#pragma unroll
                                for (int y = 0; y < 3; y++)
                                    acc += M3F(r, x, y, k) * M3F(s, x, y, l);
                            A[k][l] = acc;
                        }
#pragma unroll
                    for (int t = 0; t < 5; t++) {
                        float acc = 0.f;
#pragma unroll
                        for (int k = 0; k < 3; k++)
#pragma unroll
                            for (int l = 0; l < 3; l++)
                                acc += A[k][l] * M2F(t, k, l);
                        F[pos++] = acc;
                    }
                }
        } else {
            int pos = 235;
            float m1[5][3], m2[5][6], m3[5][10];
#pragma unroll
            for (int r = 0; r < 5; r++) {
#pragma unroll
                for (int i = 0; i < 3; i++) m1[r][i] = v[r * 20 + 1 + i];
#pragma unroll
                for (int q = 0; q < 6; q++) m2[r][q] = v[r * 20 + 4 + q];
#pragma unroll
                for (int q = 0; q < 10; q++) m3[r][q] = v[r * 20 + 10 + q];
            }
#pragma unroll
            for (int r = 0; r < 5; r++)
#pragma unroll
                for (int s = 0; s < 5; s++) {
                    float B[3];
#pragma unroll
                    for (int k = 0; k < 3; k++) {
                        float acc = 0.f;
#pragma unroll
                        for (int x = 0; x < 3; x++)
#pragma unroll
                            for (int y = 0; y < 3; y++)
                                acc += M3F(r, x, y, k) * M2F(s, x, y);
                        B[k] = acc;
                    }
#pragma unroll
                    for (int t = 0; t < 5; t++)
                        F[pos++] = B[0] * m1[t][0] + B[1] * m1[t][1] + B[2] * m1[t][2];
                }
        }
    }
    __syncthreads();

    // coalesced writeout: plain fp16, two features per lane-word
    const int wid = tid >> 5, lane = tid & 31;
    for (int al = wid; al < 32; al += 6) {
        int ga = blockIdx.x * 32 + al;
        if (ga >= NA) continue;
        char* rowb = (char*)g_A1 + (size_t)ga * (KP1 * 2);
        const float* src = sf + al * SFLD;
        for (int k2 = lane; k2 < 180; k2 += 32) {
            uint32_t h0 = h16(src[2 * k2] * IN_SCALE);
            uint32_t h1 = h16(src[2 * k2 + 1] * IN_SCALE);
            *(uint32_t*)(rowb + (size_t)k2 * 4) = h0 | (h1 << 16);
        }
    }
}

// ---------------------------------------------------------------------------
// mma.sync fp16 GEMM: 512 threads, 16 warps (4m x 4n), warp tile 32x32.
// Block 128x128, k-tile 64, 3-stage ring, one barrier per k-tile, 32 warps/SM.
// mode 1: swish -> fp16 rows scaled 2^-8
// mode 2: swish -> fused W3 GEMV (redf) + per-m-tile last-CTA writes out[]
// ---------------------------------------------------------------------------
#define ROWB 144
#define BOFF  (128 * ROWB)           // 18432
#define STAGE (2 * 128 * ROWB)       // 36864
#define GSMEM (3 * STAGE)            // 110592

__device__ __forceinline__ void load_stage(uint32_t sb, const char* Ab, const char* Bb,
                                           int m0, int bn, int ldab, int kt, int stg,
                                           int tid) {
    uint32_t st = (uint32_t)stg * STAGE;
    int k0B = kt * 128;
#pragma unroll
    for (int i = 0; i < 2; i++) {
        int t = tid + i * 512;
        int row = t >> 3, ch = (t & 7) * 16;
        CP16(sb + st + (uint32_t)(row * ROWB + ch),
             Ab + (size_t)(m0 + row) * ldab + k0B + ch);
    }
#pragma unroll
    for (int i = 0; i < 2; i++) {
        int t = tid + i * 512;
        int row = t >> 3, ch = (t & 7) * 16;
        CP16(sb + st + BOFF + (uint32_t)(row * ROWB + ch),
             Bb + (size_t)(bn * 128 + row) * ldab + k0B + ch);
    }
    CP_COMMIT();
}

__global__ void __launch_bounds__(512, 2) gemm_mma(
    const __half* __restrict__ A, const __half* __restrict__ B,
    const float* __restrict__ bias, const float* __restrict__ W3,
    char* __restrict__ Cout, const int* __restrict__ Z,
    const float* __restrict__ b3, float* __restrict__ out,
    int Kp, float scale, int mode) {
    extern __shared__ __align__(16) char smem[];
    __shared__ int s_last;
    uint32_t sb = smem_u32(smem);

    const int tid = threadIdx.x, wid = tid >> 5, lane = tid & 31;
    const int wm = wid & 3, wn = wid >> 2;          // warp grid 4(m) x 4(n)
    const int bn = blockIdx.x, m0 = blockIdx.y * 128;
    const int ldab = Kp * 2;
    const int nk = Kp >> 6;                         // k-tile = 64

    GDC_WAIT();   // needs A from predecessor (p2feat / gemm1)

    const char* Ab = (const char*)A;
    const char* Bb = (const char*)B;

    float d[2][4][4];
#pragma unroll
    for (int i = 0; i < 2; i++)
#pragma unroll
        for (int j = 0; j < 4; j++)
#pragma unroll
            for (int q = 0; q < 4; q++) d[i][j][q] = 0.f;

    load_stage(sb, Ab, Bb, m0, bn, ldab, 0, 0, tid);
    load_stage(sb, Ab, Bb, m0, bn, ldab, 1, 1, tid);

    const int lr = lane & 15, lc = lane >> 4;
    uint32_t aAdr[2], bAdr[2];
#pragma unroll
    for (int mi = 0; mi < 2; mi++)
        aAdr[mi] = sb + (uint32_t)((wm * 32 + mi * 16 + lr) * ROWB + lc * 16);
#pragma unroll
    for (int pi = 0; pi < 2; pi++)
        bAdr[pi] = sb + BOFF + (uint32_t)((wn * 32 + pi * 16 + lr) * ROWB + lc * 16);

    int s_cur = 0, s_ld = 2;
    for (int kt = 0; kt < nk; kt++) {
        CP_WAIT(1);
        __syncthreads();
        const uint32_t so = (uint32_t)s_cur * STAGE;
#pragma unroll
        for (int h = 0; h < 4; h++) {
            const uint32_t ho = so + h * 32;
            uint32_t a[2][4];
#pragma unroll
            for (int mi = 0; mi < 2; mi++)
                ldm_x4(a[mi][0], a[mi][1], a[mi][2], a[mi][3], aAdr[mi] + ho);
            uint32_t b[4][2];
#pragma unroll
            for (int pi = 0; pi < 2; pi++) {
                uint32_t t0, t1, t2, t3;
                ldm_x4(t0, t1, t2, t3, bAdr[pi] + ho);
                b[2 * pi][0] = t0; b[2 * pi][1] = t2;
                b[2 * pi + 1][0] = t1; b[2 * pi + 1][1] = t3;
            }
#pragma unroll
            for (int mi = 0; mi < 2; mi++)
#pragma unroll
                for (int ni = 0; ni < 4; ni++)
                    mma16816(d[mi][ni], a[mi], b[ni]);
        }
        if (kt + 2 < nk) load_stage(sb, Ab, Bb, m0, bn, ldab, kt + 2, s_ld, tid);
        else CP_COMMIT();
        if (++s_cur == 3) s_cur = 0;
        if (++s_ld == 3) s_ld = 0;
    }

    // epilogue
    const int g = lane >> 2, tg = lane & 3;
    float oacc[2][2] = {{0.f, 0.f}, {0.f, 0.f}};
#pragma unroll
    for (int mi = 0; mi < 2; mi++) {
#pragma unroll
        for (int ni = 0; ni < 4; ni++) {
            int n = bn * 128 + wn * 32 + ni * 8 + 2 * tg;
            float bz0 = 0.1f * bias[n], bz1 = 0.1f * bias[n + 1];
            float w30 = 0.f, w31 = 0.f;
            if (mode == 2) { w30 = W3[n]; w31 = W3[n + 1]; }
#pragma unroll
            for (int half = 0; half < 2; half++) {
                int m = m0 + wm * 32 + mi * 16 + g + half * 8;
                float v0 = d[mi][ni][2 * half + 0] * scale + bz0;
                float v1 = d[mi][ni][2 * half + 1] * scale + bz1;
                v0 = v0 / (1.0f + __expf(-v0));
                v1 = v1 / (1.0f + __expf(-v1));
                if (mode == 1) {
                    if (m < NA) {
                        uint32_t H0 = h16(v0 * IN_SCALE);
                        uint32_t H1 = h16(v1 * IN_SCALE);
                        *(uint32_t*)(Cout + (size_t)m * (KP2 * 2) + (size_t)n * 2) =
                            H0 | (H1 << 16);
                    }
                } else {
                    oacc[mi][half] += v0 * w30 + v1 * w31;
                }
            }
        }
    }
    if (mode == 2) {
#pragma unroll
        for (int mi = 0; mi < 2; mi++)
#pragma unroll
            for (int half = 0; half < 2; half++) {
                float s = oacc[mi][half];
                s += __shfl_xor_sync(0xffffffffu, s, 1);
                s += __shfl_xor_sync(0xffffffffu, s, 2);
                if (tg == 0) {
                    int m = m0 + wm * 32 + mi * 16 + g + half * 8;
                    if (m < NA) redf(&g_outacc[m], s);
                }
            }
        // per-m-tile last-CTA finalization (replaces fin_kernel)
        __threadfence();
        __syncthreads();
        if (tid == 0) {
            int prev = atomicAdd(&g_tilecnt[blockIdx.y], 1);
            s_last = (prev == 3) ? 1 : 0;
        }
        __syncthreads();
        if (s_last) {
            __threadfence();
            float bb = 0.1f * b3[0];
            for (int i = tid; i < 128; i += 512) {
                int m = m0 + i;
                if (m < NA) {
                    float v = g_outacc[m] * 0.04419417382415922f + bb;
                    out[m] = (Z[m] > 0) ? v : 0.0f;
                }
            }
        }
    }
}

// ---------------------------------------------------------------------------
extern "C" void kernel_launch(void* const* d_in, const int* in_sizes, int n_in,
                              void* d_out, int out_size) {
    const float* R   = (const float*)d_in[0];
    const int*   Z   = (const int*)d_in[1];
    const int*   nbr = (const int*)d_in[2];
    const float* off = (const float*)d_in[4];
    const float* emb = (const float*)d_in[5];
    const float* W1  = (const float*)d_in[6];
    const float* b1  = (const float*)d_in[7];
    const float* W2  = (const float*)d_in[8];
    const float* b2  = (const float*)d_in[9];
    const float* W3  = (const float*)d_in[10];
    const float* b3  = (const float*)d_in[11];
    float* out = (float*)d_out;

    cudaFuncSetAttribute(gemm_mma, cudaFuncAttributeMaxDynamicSharedMemorySize, GSMEM);
    cudaFuncSetAttribute(p2feat_kernel, cudaFuncAttributeMaxDynamicSharedMemorySize, PFSMEM);

    __half *pA1, *pB1, *pA2, *pB2;
    cudaGetSymbolAddress((void**)&pA1, g_A1);
    cudaGetSymbolAddress((void**)&pB1, g_B1);
    cudaGetSymbolAddress((void**)&pA2, g_A2);
    cudaGetSymbolAddress((void**)&pB2, g_B2);

    const float s1 = 256.0f * 0.05270462766947299f;  // 2^8 / sqrt(360)
    const float s2 = 256.0f * 0.04419417382415922f;  // 2^8 / sqrt(512)

    // PDL launch config (programmatic stream serialization, implicit trigger)
    cudaLaunchAttribute pdlAttr;
    pdlAttr.id = cudaLaunchAttributeProgrammaticStreamSerialization;
    pdlAttr.val.programmaticStreamSerializationAllowed = 1;

    prep_kernel<<<(EMBP_N + 255) / 256, 256>>>(R, Z, emb);

    {
        cudaLaunchConfig_t cfg = {};
        cfg.gridDim = dim3(P1_BLOCKS + W_BLOCKS, 1, 1);
        cfg.blockDim = dim3(256, 1, 1);
        cfg.attrs = &pdlAttr; cfg.numAttrs = 1;
        cudaLaunchKernelEx(&cfg, p1w_kernel, nbr, off, W1, W2);
    }
    {
        cudaLaunchConfig_t cfg = {};
        cfg.gridDim = dim3((NA + 31) / 32, 1, 1);
        cfg.blockDim = dim3(192, 1, 1);
        cfg.dynamicSmemBytes = PFSMEM;
        cfg.attrs = &pdlAttr; cfg.numAttrs = 1;
        cudaLaunchKernelEx(&cfg, p2feat_kernel);
    }
    {
        cudaLaunchConfig_t cfg = {};
        cfg.gridDim = dim3(4, NAP / 128, 1);
        cfg.blockDim = dim3(512, 1, 1);
        cfg.dynamicSmemBytes = GSMEM;
        cfg.attrs = &pdlAttr; cfg.numAttrs = 1;
        cudaLaunchKernelEx(&cfg, gemm_mma,
                           (const __half*)pA1, (const __half*)pB1, b1, (const float*)nullptr,
                           (char*)pA2, (const int*)nullptr, (const float*)nullptr,
                           (float*)nullptr, (int)KP1, s1, 1);
    }
    {
        cudaLaunchConfig_t cfg = {};
        cfg.gridDim = dim3(4, NAP / 128, 1);
        cfg.blockDim = dim3(512, 1, 1);
        cfg.dynamicSmemBytes = GSMEM;
        cfg.attrs = &pdlAttr; cfg.numAttrs = 1;
        cudaLaunchKernelEx(&cfg, gemm_mma,
                           (const __half*)pA2, (const __half*)pB2, b2, W3,
                           (char*)nullptr, Z, b3, out, (int)KP2, s2, 2);
    }
}

// round 16
// speedup vs baseline: 1.4968x; 1.4968x over previous
#include <cuda_runtime.h>
#include <cuda_fp16.h>
#include <math.h>
#include <stdint.h>

#define NA 20000
#define NAP 20096           // padded rows (157*128)
#define NP 800000
#define NSP 119
#define NB 7
#define RMAXV 6.0f
#define PI_F 3.14159265358979323846f
#define CAP 64              // per-atom neighbor capacity (lambda~15, P(>=64)~1e-20)

#define KP1 384             // 360 padded to 64-element k-tiles (plain fp16)
#define KP2 512
#define U 512
#define IN_SCALE 0.00390625f   // 2^-8 applied to GEMM A inputs

#define P1_BLOCKS 3125
#define W1_ELEMS (360 * 512)
#define W2_ELEMS (512 * 512)
#define W_BLOCKS ((W1_ELEMS + W2_ELEMS + 255) / 256)   // 1744

// ---------------------------------------------------------------------------
// device scratch (static; zero at module load; pads never written)
// ---------------------------------------------------------------------------
__device__ int    g_cur[NA];
__device__ float  g_outacc[NA];
__device__ float4 g_Rz[NA];                       // packed R.xyz + Z bits
__device__ float  g_embp[NSP * NSP * 36];         // emb rows padded 35->36
__device__ float  g_prod[(size_t)NA * CAP * 8];   // per active pair: rad[5]+dn[3]
__device__ __half g_A1[(size_t)NAP * KP1];        // feats (scaled), plain fp16
__device__ __half g_B1[(size_t)U * KP1];          // W1^T fp16
__device__ __half g_A2[(size_t)NAP * KP2];        // h1 (scaled), plain fp16
__device__ __half g_B2[(size_t)U * KP2];          // W2^T fp16

// ---------------------------------------------------------------------------
// helpers
// ---------------------------------------------------------------------------
__device__ __forceinline__ uint32_t smem_u32(const void* p) {
    uint32_t a;
    asm("{ .reg .u64 t; cvta.to.shared.u64 t, %1; cvt.u32.u64 %0, t; }" : "=r"(a) : "l"(p));
    return a;
}
#define CP16(dst, src)   asm volatile("cp.async.cg.shared.global [%0], [%1], 16;" :: "r"(dst), "l"(src))
#define CP_COMMIT()      asm volatile("cp.async.commit_group;" ::: "memory")
#define CP_WAIT(n)       asm volatile("cp.async.wait_group %0;" :: "n"(n) : "memory")

__device__ __forceinline__ void ldm_x4(uint32_t& r0, uint32_t& r1, uint32_t& r2, uint32_t& r3,
                                       uint32_t addr) {
    asm volatile("ldmatrix.sync.aligned.m8n8.x4.shared.b16 {%0,%1,%2,%3}, [%4];"
                 : "=r"(r0), "=r"(r1), "=r"(r2), "=r"(r3) : "r"(addr));
}
__device__ __forceinline__ void mma16816(float* d, const uint32_t* a, const uint32_t* b) {
    asm volatile("mma.sync.aligned.m16n8k16.row.col.f32.f16.f16.f32 "
                 "{%0,%1,%2,%3}, {%4,%5,%6,%7}, {%8,%9}, {%0,%1,%2,%3};"
                 : "+f"(d[0]), "+f"(d[1]), "+f"(d[2]), "+f"(d[3])
                 : "r"(a[0]), "r"(a[1]), "r"(a[2]), "r"(a[3]), "r"(b[0]), "r"(b[1]));
}
__device__ __forceinline__ void redf(float* p, float v) {
    asm volatile("red.global.add.f32 [%0], %1;" :: "l"(p), "f"(v) : "memory");
}
__device__ __forceinline__ uint32_t h16(float v) {
    return (uint32_t)__half_as_ushort(__float2half(v));
}

// symmetric index maps (compile-time folded)
__device__ __forceinline__ int imap2(int a, int b) {
    int i = a < b ? a : b, j = a < b ? b : a;
    return (i == 0) ? j : ((i == 1) ? (2 + j) : 5);
}
__device__ __forceinline__ int imap3(int a, int b, int c) {
    int i = a, j = b, k = c, t;
    if (i > j) { t = i; i = j; j = t; }
    if (j > k) { t = j; j = k; k = t; }
    if (i > j) { t = i; i = j; j = t; }
    if (i == 0) return imap2(j, k);
    if (i == 1) return (j == 1) ? (5 + k) : 8;
    return 9;
}

// ---------------------------------------------------------------------------
// prep: zero counters/outacc, pack R+Z, pad emb rows 35->36 (one kernel)
// ---------------------------------------------------------------------------
#define EMBP_N (NSP * NSP * 36)
__global__ void prep_kernel(const float* __restrict__ R, const int* __restrict__ Z,
                            const float* __restrict__ emb) {
    int i = blockIdx.x * blockDim.x + threadIdx.x;
    if (i < EMBP_N) {
        int pair = i / 36, c = i - pair * 36;
        g_embp[i] = (c < 35) ? emb[(size_t)pair * 35 + c] : 0.f;
    }
    if (i < NA) {
        g_cur[i] = 0;
        g_outacc[i] = 0.f;
        g_Rz[i] = make_float4(R[3 * i], R[3 * i + 1], R[3 * i + 2], __int_as_float(Z[i]));
    }
}

// ---------------------------------------------------------------------------
// p1 + wprep fused by block range. Direct 7-expf basis.
// ---------------------------------------------------------------------------
__global__ void p1w_kernel(const int* __restrict__ nbr, const float* __restrict__ off,
                           const float* __restrict__ W1, const float* __restrict__ W2) {
    if (blockIdx.x >= P1_BLOCKS) {
        int idx = (blockIdx.x - P1_BLOCKS) * 256 + threadIdx.x;
        if (idx < W1_ELEMS) {
            int n = idx / 360, k = idx - n * 360;
            float w = __ldg(W1 + (size_t)k * 512 + n);
            *(__half*)((char*)g_B1 + (size_t)n * (KP1 * 2) + 2 * k) = __float2half(w);
        } else {
            idx -= W1_ELEMS;
            if (idx < W2_ELEMS) {
                int n = idx >> 9, k = idx & 511;
                float w = __ldg(W2 + (size_t)k * 512 + n);
                *(__half*)((char*)g_B2 + (size_t)n * (KP2 * 2) + 2 * k) = __float2half(w);
            }
        }
        return;
    }

    int p = blockIdx.x * blockDim.x + threadIdx.x;
    if (p >= NP) return;
    int ia = nbr[p], ja = nbr[NP + p];

    float4 ri = __ldg(&g_Rz[ia]);
    float4 rj = __ldg(&g_Rz[ja]);
    float dx = rj.x - ri.x + off[p * 3 + 0];
    float dy = rj.y - ri.y + off[p * 3 + 1];
    float dz = rj.z - ri.z + off[p * 3 + 2];
    float dr = sqrtf(dx * dx + dy * dy + dz * dz);
    if (!(dr < RMAXV)) return;

    float inv = 1.0f / (dr + 1e-5f);
    float dn0 = dx * inv, dn1 = dy * inv, dn2 = dz * inv;

    const float betta = 49.0f / 36.0f;
    const float rad_norm = 0.898112f;   // (2*betta/pi)^0.75
    float cut = 0.5f * (cosf(PI_F * dr * (1.0f / RMAXV)) + 1.0f);

    float basis[NB];
#pragma unroll
    for (int b = 0; b < NB; b++) {
        float t = dr - (0.5f + 0.91666666666666667f * (float)b);
        basis[b] = rad_norm * expf(-betta * t * t);
    }

    int zi = __float_as_int(ri.w), zj = __float_as_int(rj.w);
    const float4* e4 = (const float4*)(g_embp + (size_t)(zj * NSP + zi) * 36);
    float ev[36];
#pragma unroll
    for (int q = 0; q < 9; q++) {
        float4 t = __ldg(e4 + q);
        ev[4 * q] = t.x; ev[4 * q + 1] = t.y; ev[4 * q + 2] = t.z; ev[4 * q + 3] = t.w;
    }

    float pref = 0.37796447300922720f * cut;
    float rad[5];
#pragma unroll
    for (int r = 0; r < 5; r++) {
        float s = 0.f;
#pragma unroll
        for (int b = 0; b < NB; b++) s += ev[r * NB + b] * basis[b];
        rad[r] = pref * s;
    }

    int slot = atomicAdd(&g_cur[ia], 1);
    if (slot >= CAP) return;   // statistically impossible (P ~ 1e-20)
    float* pb = g_prod + ((size_t)ia * CAP + slot) * 8;
    ((float4*)pb)[0] = make_float4(rad[0], rad[1], rad[2], rad[3]);
    ((float4*)pb)[1] = make_float4(rad[4], dn0, dn1, dn2);
}

// ---------------------------------------------------------------------------
// fused p2+feat: 192 threads / 32 atoms per block
// ---------------------------------------------------------------------------
#define M2F(r, x, y) m2[r][imap2((x), (y))]
#define M3F(r, x, y, z) m3[r][imap3((x), (y), (z))]
#define MLD 101
#define SFLD 361
#define PFSMEM ((32 * MLD + 32 * SFLD) * 4)

__global__ void __launch_bounds__(192) p2feat_kernel() {
    extern __shared__ float sm[];
    float* smM = sm;                 // [32][MLD]
    float* sf = sm + 32 * MLD;       // [32][SFLD]
    const int tid = threadIdx.x;

    if (tid < 160) {
        int aL = tid / 5, r = tid - aL * 5;
        int a = blockIdx.x * 32 + aL;
        if (a < NA) {
            int n = g_cur[a];
            if (n > CAP) n = CAP;
            const float* base = g_prod + (size_t)a * CAP * 8;
            float acc[20];
#pragma unroll
            for (int j = 0; j < 20; j++) acc[j] = 0.f;
            for (int s = 0; s < n; s++) {
                float rv = __ldg(base + s * 8 + r);
                float4 v = __ldg((const float4*)(base + s * 8 + 4));
                float dn0 = v.y, dn1 = v.z, dn2 = v.w;
                float q00 = dn0 * dn0, q01 = dn0 * dn1, q02 = dn0 * dn2;
                float q11 = dn1 * dn1, q12 = dn1 * dn2, q22 = dn2 * dn2;
                acc[0] += rv;
                acc[1] += rv * dn0;  acc[2] += rv * dn1;  acc[3] += rv * dn2;
                acc[4] += rv * q00;  acc[5] += rv * q01;  acc[6] += rv * q02;
                acc[7] += rv * q11;  acc[8] += rv * q12;  acc[9] += rv * q22;
                acc[10] += rv * q00 * dn0;  acc[11] += rv * q00 * dn1;  acc[12] += rv * q00 * dn2;
                acc[13] += rv * q11 * dn0;  acc[14] += rv * q01 * dn2;  acc[15] += rv * q22 * dn0;
                acc[16] += rv * q11 * dn1;  acc[17] += rv * q11 * dn2;  acc[18] += rv * q22 * dn1;
                acc[19] += rv * q22 * dn2;
            }
            float* dst = smM + aL * MLD + r * 20;
#pragma unroll
            for (int j = 0; j < 20; j++) dst[j] = acc[j];
        }
    }
    __syncthreads();

    const int role = tid >> 5;
    const int aL = tid & 31;
    const int a = blockIdx.x * 32 + aL;
    if (role < 4 && a < NA) {
        const float* v = smM + aL * MLD;
        float* F = sf + aL * SFLD;
        if (role == 0) {
            int pos = 0;
            float m0[5];
#pragma unroll
            for (int r = 0; r < 5; r++) m0[r] = v[r * 20];
#pragma unroll
            for (int r = 0; r < 5; r++) F[pos++] = m0[r];
            float m1[5][3];
#pragma unroll
            for (int r = 0; r < 5; r++)
#pragma unroll
                for (int i = 0; i < 3; i++) m1[r][i] = v[r * 20 + 1 + i];
#pragma unroll
            for (int r = 0; r < 5; r++)
#pragma unroll
                for (int s = 0; s <= r; s++) {
                    float acc = 0.f;
#pragma unroll
                    for (int i = 0; i < 3; i++) acc += m1[r][i] * m1[s][i];
                    F[pos++] = acc;
                }
            float m2[5][6];
#pragma unroll
            for (int r = 0; r < 5; r++)
#pragma unroll
                for (int q = 0; q < 6; q++) m2[r][q] = v[r * 20 + 4 + q];
            const float w2[6] = {1.f, 2.f, 2.f, 1.f, 2.f, 1.f};
#pragma unroll
            for (int r = 0; r < 5; r++)
#pragma unroll
                for (int s = 0; s <= r; s++) {
                    float acc = 0.f;
#pragma unroll
                    for (int q = 0; q < 6; q++) acc += w2[q] * m2[r][q] * m2[s][q];
                    F[pos++] = acc;
                }
            {
                float m3[5][10];
#pragma unroll
                for (int r = 0; r < 5; r++)
#pragma unroll
                    for (int q = 0; q < 10; q++) m3[r][q] = v[r * 20 + 10 + q];
                const float w3[10] = {1.f, 3.f, 3.f, 3.f, 6.f, 3.f, 1.f, 3.f, 3.f, 1.f};
#pragma unroll
                for (int r = 0; r < 5; r++)
#pragma unroll
                    for (int s = 0; s <= r; s++) {
                        float acc = 0.f;
#pragma unroll
                        for (int q = 0; q < 10; q++) acc += w3[q] * m3[r][q] * m3[s][q];
                        F[pos++] = acc;
                    }
            }
#pragma unroll
            for (int r = 0; r < 5; r++)
#pragma unroll
                for (int s = 0; s <= r; s++)
#pragma unroll
                    for (int t = 0; t <= s; t++) {
                        float acc = 0.f;
#pragma unroll
                        for (int x = 0; x < 3; x++)
#pragma unroll
                            for (int y = 0; y < 3; y++)
#pragma unroll
                                for (int z = 0; z < 3; z++)
                                    acc += M2F(r, x, y) * M2F(s, x, z) * M2F(t, y, z);
                        F[pos++] = acc;
                    }
        } else if (role == 1) {
            int pos = 85;
            float m1[5][3], m2[5][6];
#pragma unroll
            for (int r = 0; r < 5; r++) {
#pragma unroll
                for (int i = 0; i < 3; i++) m1[r][i] = v[r * 20 + 1 + i];
#pragma unroll
                for (int q = 0; q < 6; q++) m2[r][q] = v[r * 20 + 4 + q];
            }
#pragma unroll
            for (int r = 0; r < 5; r++)
#pragma unroll
                for (int s = 0; s <= r; s++)
#pragma unroll
                    for (int t = 0; t < 5; t++) {
                        float acc = 0.f;
#pragma unroll
                        for (int x = 0; x < 3; x++)
#pragma unroll
                            for (int y = 0; y < 3; y++)
                                acc += m1[r][x] * m1[s][y] * M2F(t, x, y);
                        F[pos++] = acc;
                    }
        } else if (role == 2) {
            int pos = 160;
            float m2[5][6], m3[5][10];
#pragma unroll
            for (int r = 0; r < 5; r++) {
#pragma unroll
                for (int q = 0; q < 6; q++) m2[r][q] = v[r * 20 + 4 + q];
#pragma unroll
                for (int q = 0; q < 10; q++) m3[r][q] = v[r * 20 + 10 + q];
            }
#pragma unroll
            for (int r = 0; r < 5; r++)
#pragma unroll
                for (int s = 0; s <= r; s++) {
                    float A[3][3];
#pragma unroll
                    for (int k = 0; k < 3; k++)
#pragma unroll
                        for (int l = 0; l < 3; l++) {
                            float acc = 0.f;
#pragma unroll
                            for (int x = 0; x < 3; x++)
#pragma unroll
                                for (int y = 0; y < 3; y++)
                                    acc += M3F(r, x, y, k) * M3F(s, x, y, l);
                            A[k][l] = acc;
                        }
#pragma unroll
                    for (int t = 0; t < 5; t++) {
                        float acc = 0.f;
#pragma unroll
                        for (int k = 0; k < 3; k++)
#pragma unroll
                            for (int l = 0; l < 3; l++)
                                acc += A[k][l] * M2F(t, k, l);
                        F[pos++] = acc;
                    }
                }
        } else {
            int pos = 235;
            float m1[5][3], m2[5][6], m3[5][10];
#pragma unroll
            for (int r = 0; r < 5; r++) {
#pragma unroll
                for (int i = 0; i < 3; i++) m1[r][i] = v[r * 20 + 1 + i];
#pragma unroll
                for (int q = 0; q < 6; q++) m2[r][q] = v[r * 20 + 4 + q];
#pragma unroll
                for (int q = 0; q < 10; q++) m3[r][q] = v[r * 20 + 10 + q];
            }
#pragma unroll
            for (int r = 0; r < 5; r++)
#pragma unroll
                for (int s = 0; s < 5; s++) {
                    float B[3];
#pragma unroll
                    for (int k = 0; k < 3; k++) {
                        float acc = 0.f;
#pragma unroll
                        for (int x = 0; x < 3; x++)
#pragma unroll
                            for (int y = 0; y < 3; y++)
                                acc += M3F(r, x, y, k) * M2F(s, x, y);
                        B[k] = acc;
                    }
#pragma unroll
                    for (int t = 0; t < 5; t++)
                        F[pos++] = B[0] * m1[t][0] + B[1] * m1[t][1] + B[2] * m1[t][2];
                }
        }
    }
    __syncthreads();

    // coalesced writeout: plain fp16, two features per lane-word
    const int wid = tid >> 5, lane = tid & 31;
    for (int al = wid; al < 32; al += 6) {
        int ga = blockIdx.x * 32 + al;
        if (ga >= NA) continue;
        char* rowb = (char*)g_A1 + (size_t)ga * (KP1 * 2);
        const float* src = sf + al * SFLD;
        for (int k2 = lane; k2 < 180; k2 += 32) {
            uint32_t h0 = h16(src[2 * k2] * IN_SCALE);
            uint32_t h1 = h16(src[2 * k2 + 1] * IN_SCALE);
            *(uint32_t*)(rowb + (size_t)k2 * 4) = h0 | (h1 << 16);
        }
    }
}

// ---------------------------------------------------------------------------
// mma.sync fp16 GEMM: 512 threads, 16 warps (4m x 4n), warp tile 32x32.
// Block tile 128x128, k-tile 64, 3-stage ring, one barrier per k-tile.
// __launch_bounds__(512,2) -> 32 warps/SM.
// mode 1: swish -> fp16 rows scaled 2^-8; mode 2: fused W3 GEMV
// ---------------------------------------------------------------------------
#define ROWB 144
#define BOFF  (128 * ROWB)           // 18432
#define STAGE (2 * 128 * ROWB)       // 36864
#define GSMEM (3 * STAGE)            // 110592

__device__ __forceinline__ void load_stage(uint32_t sb, const char* Ab, const char* Bb,
                                           int m0, int bn, int ldab, int kt, int stg,
                                           int tid) {
    uint32_t st = (uint32_t)stg * STAGE;
    int k0B = kt * 128;
#pragma unroll
    for (int i = 0; i < 2; i++) {
        int t = tid + i * 512;
        int row = t >> 3, ch = (t & 7) * 16;
        CP16(sb + st + (uint32_t)(row * ROWB + ch),
             Ab + (size_t)(m0 + row) * ldab + k0B + ch);
    }
#pragma unroll
    for (int i = 0; i < 2; i++) {
        int t = tid + i * 512;
        int row = t >> 3, ch = (t & 7) * 16;
        CP16(sb + st + BOFF + (uint32_t)(row * ROWB + ch),
             Bb + (size_t)(bn * 128 + row) * ldab + k0B + ch);
    }
    CP_COMMIT();
}

__global__ void __launch_bounds__(512, 2) gemm_mma(
    const __half* __restrict__ A, const __half* __restrict__ B,
    const float* __restrict__ bias, const float* __restrict__ W3,
    char* __restrict__ Cout, int Kp, float scale, int mode) {
    extern __shared__ __align__(16) char smem[];
    uint32_t sb = smem_u32(smem);

    const int tid = threadIdx.x, wid = tid >> 5, lane = tid & 31;
    const int wm = wid & 3, wn = wid >> 2;          // warp grid 4(m) x 4(n)
    const int bn = blockIdx.x, m0 = blockIdx.y * 128;
    const int ldab = Kp * 2;
    const int nk = Kp >> 6;                         // k-tile = 64

    const char* Ab = (const char*)A;
    const char* Bb = (const char*)B;

    float d[2][4][4];
#pragma unroll
    for (int i = 0; i < 2; i++)
#pragma unroll
        for (int j = 0; j < 4; j++)
#pragma unroll
            for (int q = 0; q < 4; q++) d[i][j][q] = 0.f;

    load_stage(sb, Ab, Bb, m0, bn, ldab, 0, 0, tid);
    load_stage(sb, Ab, Bb, m0, bn, ldab, 1, 1, tid);

    const int lr = lane & 15, lc = lane >> 4;
    uint32_t aAdr[2], bAdr[2];
#pragma unroll
    for (int mi = 0; mi < 2; mi++)
        aAdr[mi] = sb + (uint32_t)((wm * 32 + mi * 16 + lr) * ROWB + lc * 16);
#pragma unroll
    for (int pi = 0; pi < 2; pi++)
        bAdr[pi] = sb + BOFF + (uint32_t)((wn * 32 + pi * 16 + lr) * ROWB + lc * 16);

    int s_cur = 0, s_ld = 2;
    for (int kt = 0; kt < nk; kt++) {
        CP_WAIT(1);
        __syncthreads();
        const uint32_t so = (uint32_t)s_cur * STAGE;
#pragma unroll
        for (int h = 0; h < 4; h++) {
            const uint32_t ho = so + h * 32;
            uint32_t a[2][4];
#pragma unroll
            for (int mi = 0; mi < 2; mi++)
                ldm_x4(a[mi][0], a[mi][1], a[mi][2], a[mi][3], aAdr[mi] + ho);
            uint32_t b[4][2];
#pragma unroll
            for (int pi = 0; pi < 2; pi++) {
                uint32_t t0, t1, t2, t3;
                ldm_x4(t0, t1, t2, t3, bAdr[pi] + ho);
                b[2 * pi][0] = t0; b[2 * pi][1] = t2;
                b[2 * pi + 1][0] = t1; b[2 * pi + 1][1] = t3;
            }
#pragma unroll
            for (int mi = 0; mi < 2; mi++)
#pragma unroll
                for (int ni = 0; ni < 4; ni++)
                    mma16816(d[mi][ni], a[mi], b[ni]);
        }
        // 3-stage ring, single barrier: load for kt+2 targets stage (kt-1)%3,
        // whose readers all passed this iteration's barrier.
        if (kt + 2 < nk) load_stage(sb, Ab, Bb, m0, bn, ldab, kt + 2, s_ld, tid);
        else CP_COMMIT();
        if (++s_cur == 3) s_cur = 0;
        if (++s_ld == 3) s_ld = 0;
    }

    // epilogue
    const int g = lane >> 2, tg = lane & 3;
    float oacc[2][2] = {{0.f, 0.f}, {0.f, 0.f}};
#pragma unroll
    for (int mi = 0; mi < 2; mi++) {
#pragma unroll
        for (int ni = 0; ni < 4; ni++) {
            int n = bn * 128 + wn * 32 + ni * 8 + 2 * tg;
            float bz0 = 0.1f * bias[n], bz1 = 0.1f * bias[n + 1];
            float w30 = 0.f, w31 = 0.f;
            if (mode == 2) { w30 = W3[n]; w31 = W3[n + 1]; }
#pragma unroll
            for (int half = 0; half < 2; half++) {
                int m = m0 + wm * 32 + mi * 16 + g + half * 8;
                float v0 = d[mi][ni][2 * half + 0] * scale + bz0;
                float v1 = d[mi][ni][2 * half + 1] * scale + bz1;
                v0 = v0 / (1.0f + __expf(-v0));
                v1 = v1 / (1.0f + __expf(-v1));
                if (mode == 1) {
                    if (m < NA) {
                        uint32_t H0 = h16(v0 * IN_SCALE);
                        uint32_t H1 = h16(v1 * IN_SCALE);
                        *(uint32_t*)(Cout + (size_t)m * (KP2 * 2) + (size_t)n * 2) =
                            H0 | (H1 << 16);
                    }
                } else {
                    oacc[mi][half] += v0 * w30 + v1 * w31;
                }
            }
        }
    }
    if (mode == 2) {
#pragma unroll
        for (int mi = 0; mi < 2; mi++)
#pragma unroll
            for (int half = 0; half < 2; half++) {
                float s = oacc[mi][half];
                s += __shfl_xor_sync(0xffffffffu, s, 1);
                s += __shfl_xor_sync(0xffffffffu, s, 2);
                if (tg == 0) {
                    int m = m0 + wm * 32 + mi * 16 + g + half * 8;
                    if (m < NA) redf(&g_outacc[m], s);
                }
            }
    }
}

// ---------------------------------------------------------------------------
// finalize: out = mask * (acc / sqrt(512) + 0.1*b3)
// ---------------------------------------------------------------------------
__global__ void fin_kernel(const float* __restrict__ b3, const int* __restrict__ Z,
                           float* __restrict__ out) {
    int i = blockIdx.x * blockDim.x + threadIdx.x;
    if (i >= NA) return;
    float v = g_outacc[i] * 0.04419417382415922f + 0.1f * b3[0];
    out[i] = (Z[i] > 0) ? v : 0.0f;
}

// ---------------------------------------------------------------------------
extern "C" void kernel_launch(void* const* d_in, const int* in_sizes, int n_in,
                              void* d_out, int out_size) {
    const float* R   = (const float*)d_in[0];
    const int*   Z   = (const int*)d_in[1];
    const int*   nbr = (const int*)d_in[2];
    const float* off = (const float*)d_in[4];
    const float* emb = (const float*)d_in[5];
    const float* W1  = (const float*)d_in[6];
    const float* b1  = (const float*)d_in[7];
    const float* W2  = (const float*)d_in[8];
    const float* b2  = (const float*)d_in[9];
    const float* W3  = (const float*)d_in[10];
    const float* b3  = (const float*)d_in[11];
    float* out = (float*)d_out;

    cudaFuncSetAttribute(gemm_mma, cudaFuncAttributeMaxDynamicSharedMemorySize, GSMEM);
    cudaFuncSetAttribute(p2feat_kernel, cudaFuncAttributeMaxDynamicSharedMemorySize, PFSMEM);

    __half *pA1, *pB1, *pA2, *pB2;
    cudaGetSymbolAddress((void**)&pA1, g_A1);
    cudaGetSymbolAddress((void**)&pB1, g_B1);
    cudaGetSymbolAddress((void**)&pA2, g_A2);
    cudaGetSymbolAddress((void**)&pB2, g_B2);

    prep_kernel<<<(EMBP_N + 255) / 256, 256>>>(R, Z, emb);
    p1w_kernel<<<P1_BLOCKS + W_BLOCKS, 256>>>(nbr, off, W1, W2);
    p2feat_kernel<<<(NA + 31) / 32, 192, PFSMEM>>>();

    const float s1 = 256.0f * 0.05270462766947299f;  // 2^8 / sqrt(360)
    const float s2 = 256.0f * 0.04419417382415922f;  // 2^8 / sqrt(512)

    dim3 g(4, NAP / 128);
    gemm_mma<<<g, 512, GSMEM>>>(pA1, pB1, b1, nullptr, (char*)pA2, KP1, s1, 1);
    gemm_mma<<<g, 512, GSMEM>>>(pA2, pB2, b2, W3, nullptr, KP2, s2, 2);

    fin_kernel<<<(NA + 255) / 256, 256>>>(b3, Z, out);
}